// round 13
// baseline (speedup 1.0000x reference)
#include <cuda_runtime.h>
#include <math.h>
#include <stdint.h>

#define NPATCH 100000
#define LDIM   1024
#define HDIM   512
#define DDIM   256
#define KHEADS 5
#define NCLS   2
#define MTOP   1000
#define MDROP  600
#define NEGV   (-1.0e9f)
#define CANDC  8192

// ---------------- scratch ----------------
__device__ float g_x [(size_t)NPATCH * HDIM];
__device__ float g_ag[(size_t)NPATCH * DDIM];
__device__ float g_At[(size_t)KHEADS * NPATCH];
__device__ float g_M [KHEADS * HDIM];
__device__ float g_Wab[(size_t)512 * 512];
__device__ unsigned g_pivot[KHEADS];
__device__ unsigned g_ccnt[KHEADS];
__device__ unsigned g_mxu[KHEADS];
__device__ float g_psum[KHEADS][40];
__device__ unsigned long long g_cand[(size_t)KHEADS * CANDC];

// ---------------- helpers ----------------
__device__ __forceinline__ unsigned long long pk2(float lo, float hi) {
    unsigned long long r;
    asm("mov.b64 %0, {%1, %2};" : "=l"(r) : "f"(lo), "f"(hi));
    return r;
}
__device__ __forceinline__ void ffma2(unsigned long long& d, unsigned long long a,
                                      unsigned long long b) {
    asm("fma.rn.f32x2 %0, %1, %2, %0;" : "+l"(d) : "l"(a), "l"(b));
}
__device__ __forceinline__ float2 upk2(unsigned long long v) {
    float2 r;
    asm("mov.b64 {%0, %1}, %2;" : "=f"(r.x), "=f"(r.y) : "l"(v));
    return r;
}
__device__ __forceinline__ uint32_t smem_u32(const void* p) {
    uint32_t a;
    asm("{ .reg .u64 t; cvta.to.shared.u64 t, %1; cvt.u32.u64 %0, t; }" : "=r"(a) : "l"(p));
    return a;
}
__device__ __forceinline__ void cp16(uint32_t dst, const void* src) {
    asm volatile("cp.async.cg.shared.global [%0], [%1], 16;" :: "r"(dst), "l"(src));
}
#define CP_COMMIT() asm volatile("cp.async.commit_group;" ::: "memory")
#define CP_WAIT0()  asm volatile("cp.async.wait_group 0;" ::: "memory")

__device__ __forceinline__ unsigned f2u(float f) {
    unsigned u = __float_as_uint(f);
    return (u & 0x80000000u) ? ~u : (u | 0x80000000u);
}
__device__ __forceinline__ float u2f(unsigned u) {
    unsigned b = (u & 0x80000000u) ? (u & 0x7FFFFFFFu) : ~u;
    return __uint_as_float(b);
}

// ---------------- prep kernels ----------------
__global__ void prep_wab(const float* __restrict__ Wa, const float* __restrict__ Wb) {
    int idx = blockIdx.x * 256 + threadIdx.x;
    if (idx >= 512 * 256) return;
    int k = idx >> 8, d = idx & 255;
    g_Wab[(size_t)k * 512 + 2 * d]     = Wa[(size_t)k * 256 + d];
    g_Wab[(size_t)k * 512 + 2 * d + 1] = Wb[(size_t)k * 256 + d];
}

// ============ FFMA2 SGEMM: k-tile 32, dynamic smem, 2 CTA/SM (FROZEN) ============
#define GSM_FLOATS (2 * 8192)
#define GSM_BYTES  (GSM_FLOATS * 4)

template<int KTOT, int EPI>
__global__ void __launch_bounds__(256, 2) f2gemm(
    const float* __restrict__ A, const float* __restrict__ B,
    const float* __restrict__ bias0, const float* __restrict__ bias1,
    float* __restrict__ Out, int Mrows)
{
    extern __shared__ float smf[];           // [2][ A:32x128 | B:32x128 ]
    constexpr int NT = KTOT / 32;
    const int tid = threadIdx.x;
    const int m0 = blockIdx.y * 128;
    const int n0 = blockIdx.x * 128;
    const int tm = tid >> 4, tn = tid & 15;
    const int ar = tid >> 1, ak = (tid & 1) << 2;
    const int bk = tid >> 5;                 // 0..7
    const int bn = (tid & 31) << 2;
    const bool aval = (m0 + ar) < Mrows;
    const float* Ap = A + (size_t)(m0 + ar) * KTOT + ak;
    const float* Bp = B + (size_t)bk * 512 + n0 + bn;

    float* As0 = smf;            float* Bs0 = smf + 4096;
    float* As1 = smf + 8192;     float* Bs1 = smf + 12288;
    uint32_t bu0 = smem_u32(Bs0 + bk * 128 + bn);
    uint32_t bu1 = smem_u32(Bs1 + bk * 128 + bn);

    unsigned long long acc[8][4];
    #pragma unroll
    for (int i = 0; i < 8; i++)
        #pragma unroll
        for (int p = 0; p < 4; p++) acc[i][p] = 0ULL;

    // prologue: stage 0
    {
        #pragma unroll
        for (int o = 0; o < 4; o++) {
            float4 a = aval ? *(const float4*)(Ap + o * 8) : make_float4(0.f, 0.f, 0.f, 0.f);
            As0[(ak + o * 8 + 0) * 128 + ar] = a.x;
            As0[(ak + o * 8 + 1) * 128 + ar] = a.y;
            As0[(ak + o * 8 + 2) * 128 + ar] = a.z;
            As0[(ak + o * 8 + 3) * 128 + ar] = a.w;
            cp16(bu0 + o * 8 * 128 * 4, Bp + (size_t)o * 8 * 512);
        }
        CP_COMMIT();
    }

    for (int kt = 0; kt < NT; kt++) {
        const int buf = kt & 1;
        float* Asc = buf ? As1 : As0;
        float* Bsc = buf ? Bs1 : Bs0;
        CP_WAIT0();
        __syncthreads();
        const bool nxt = (kt + 1) < NT;
        float4 avn[4];
        if (nxt) {
            #pragma unroll
            for (int o = 0; o < 4; o++) {
                avn[o] = aval ? *(const float4*)(Ap + (size_t)(kt + 1) * 32 + o * 8)
                              : make_float4(0.f, 0.f, 0.f, 0.f);
                cp16((buf ? bu0 : bu1) + o * 8 * 128 * 4,
                     Bp + ((size_t)(kt + 1) * 32 + o * 8) * 512);
            }
            CP_COMMIT();
        }
        #pragma unroll
        for (int kk = 0; kk < 32; kk++) {
            float ra[8], rb[8];
            *(float4*)&ra[0] = *(const float4*)&Asc[kk * 128 + (tm << 2)];
            *(float4*)&ra[4] = *(const float4*)&Asc[kk * 128 + 64 + (tm << 2)];
            *(float4*)&rb[0] = *(const float4*)&Bsc[kk * 128 + (tn << 2)];
            *(float4*)&rb[4] = *(const float4*)&Bsc[kk * 128 + 64 + (tn << 2)];
            unsigned long long ap[8], bp[4];
            #pragma unroll
            for (int i = 0; i < 8; i++) ap[i] = pk2(ra[i], ra[i]);
            bp[0] = pk2(rb[0], rb[1]); bp[1] = pk2(rb[2], rb[3]);
            bp[2] = pk2(rb[4], rb[5]); bp[3] = pk2(rb[6], rb[7]);
            #pragma unroll
            for (int i = 0; i < 8; i++)
                #pragma unroll
                for (int p = 0; p < 4; p++) ffma2(acc[i][p], ap[i], bp[p]);
        }
        if (nxt) {
            float* Asn = buf ? As0 : As1;
            #pragma unroll
            for (int o = 0; o < 4; o++) {
                Asn[(ak + o * 8 + 0) * 128 + ar] = avn[o].x;
                Asn[(ak + o * 8 + 1) * 128 + ar] = avn[o].y;
                Asn[(ak + o * 8 + 2) * 128 + ar] = avn[o].z;
                Asn[(ak + o * 8 + 3) * 128 + ar] = avn[o].w;
            }
        }
    }

    // ---------------- epilogue ----------------
    #pragma unroll
    for (int i = 0; i < 8; i++) {
        const int m = m0 + ((i < 4) ? (tm << 2) + i : 64 + (tm << 2) + i - 4);
        if (m >= Mrows) continue;
        #pragma unroll
        for (int p = 0; p < 4; p++) {
            float2 v = upk2(acc[i][p]);
            const int nl = (p < 2) ? (tn << 2) + 2 * p : 64 + (tn << 2) + 2 * (p - 2);
            const int n = n0 + nl;
            if (EPI == 0) {
                v.x = fmaxf(v.x + bias0[n], 0.f);
                v.y = fmaxf(v.y + bias0[n + 1], 0.f);
                *(float2*)&Out[(size_t)m * 512 + n] = v;
            } else {
                const int d = n >> 1;
                float a = tanhf(v.x + bias0[d]);
                float g = 1.f / (1.f + expf(-(v.y + bias1[d])));
                Out[(size_t)m * 256 + d] = a * g;
            }
        }
    }
}

// ---------------- A = ag @ Wc + bc (sequential d order -- rank-stable, FROZEN) ----------------
__global__ void __launch_bounds__(256) attn_scores_k(
    const float* __restrict__ ag, const float* __restrict__ Wc,
    const float* __restrict__ bc, float* __restrict__ At)
{
    __shared__ float sW[DDIM * KHEADS];
    __shared__ float sb[KHEADS];
    for (int i = threadIdx.x; i < DDIM * KHEADS; i += blockDim.x) sW[i] = Wc[i];
    if (threadIdx.x < KHEADS) sb[threadIdx.x] = bc[threadIdx.x];
    __syncthreads();
    int n = blockIdx.x * blockDim.x + threadIdx.x;
    if (n >= NPATCH) return;
    float acc[KHEADS];
    #pragma unroll
    for (int k = 0; k < KHEADS; k++) acc[k] = sb[k];
    const float4* r = (const float4*)(ag + (size_t)n * DDIM);
    #pragma unroll 4
    for (int q = 0; q < DDIM / 4; q++) {
        float4 v = r[q];
        int d = q * 4;
        #pragma unroll
        for (int k = 0; k < KHEADS; k++) {
            acc[k] = fmaf(v.x, sW[(d + 0) * KHEADS + k], acc[k]);
            acc[k] = fmaf(v.y, sW[(d + 1) * KHEADS + k], acc[k]);
            acc[k] = fmaf(v.z, sW[(d + 2) * KHEADS + k], acc[k]);
            acc[k] = fmaf(v.w, sW[(d + 3) * KHEADS + k], acc[k]);
        }
    }
    #pragma unroll
    for (int k = 0; k < KHEADS; k++) At[(size_t)k * NPATCH + n] = acc[k];
}

// ---------------- top-k stage 1: deterministic sample pivot (+ zero g_M) ----------------
__global__ void __launch_bounds__(1024) topk_pivot_k(const float* __restrict__ At,
                                                     float* __restrict__ Mout) {
    const int k = blockIdx.x, tid = threadIdx.x;
    __shared__ unsigned sk[2048];
    if (tid < HDIM) Mout[k * HDIM + tid] = 0.f;
    for (int j = tid; j < 2048; j += 1024)
        sk[j] = (j < 1536) ? f2u(At[(size_t)k * NPATCH + j * 65]) : 0u;
    __syncthreads();
    for (int kk = 2; kk <= 2048; kk <<= 1) {
        for (int j = kk >> 1; j > 0; j >>= 1) {
            int i = ((tid & ~(j - 1)) << 1) | (tid & (j - 1));
            int l = i | j;
            unsigned a = sk[i], b = sk[l];
            bool asc = (i & kk) != 0;
            if (asc ? (a > b) : (a < b)) { sk[i] = b; sk[l] = a; }
            __syncthreads();
        }
    }
    if (tid == 0) {
        g_pivot[k] = sk[63];
        g_ccnt[k] = 0;
    }
}

// ---------------- top-k stage 2: grid-wide candidate gather ----------------
__global__ void __launch_bounds__(256) topk_gather_k(const float* __restrict__ At) {
    const int k = blockIdx.y;
    const unsigned pivot = g_pivot[k];
    const float* row = At + (size_t)k * NPATCH;
    const int base = blockIdx.x * 2500;
    for (int j = base + threadIdx.x; j < base + 2500; j += 256) {
        unsigned u = f2u(row[j]);
        if (u >= pivot) {
            unsigned p = atomicAdd(&g_ccnt[k], 1u);
            if (p < CANDC)
                g_cand[(size_t)k * CANDC + p] =
                    ((unsigned long long)u << 32) | (unsigned)(~(unsigned)j);
        }
    }
}

// ---- top-k stage 3: sort + mask + extract post-mask row max (replaces smax1) ----
__global__ void __launch_bounds__(1024) topk_mask2_k(
    float* __restrict__ At, const int* __restrict__ rand_sel)
{
    extern __shared__ unsigned long long buf[];   // 8192 + flags
    unsigned char* mk = (unsigned char*)(buf + 8192);  // 1024 flags
    const int k = blockIdx.x, tid = threadIdx.x;
    unsigned cnt = g_ccnt[k]; if (cnt > CANDC) cnt = CANDC;
    for (int i = tid; i < 8192; i += 1024)
        buf[i] = (i < (int)cnt) ? g_cand[(size_t)k * CANDC + i] : 0ULL;
    if (tid < 1024) mk[tid] = 0;
    __syncthreads();
    for (int kk = 2; kk <= 8192; kk <<= 1) {
        for (int j = kk >> 1; j > 0; j >>= 1) {
            for (int w = tid; w < 4096; w += 1024) {
                int i = ((w & ~(j - 1)) << 1) | (w & (j - 1));
                int l = i | j;
                unsigned long long a = buf[i], b = buf[l];
                bool asc = (i & kk) != 0;
                if (asc ? (a > b) : (a < b)) { buf[i] = b; buf[l] = a; }
            }
            __syncthreads();
        }
    }
    float* row = At + (size_t)k * NPATCH;
    for (int j = tid; j < MDROP; j += 1024) {
        int rs = rand_sel[k * MDROP + j];
        mk[rs] = 1;
        int idx = (int)(~(unsigned)(buf[rs] & 0xFFFFFFFFULL));
        row[idx] = NEGV;
    }
    __syncthreads();
    if (tid == 0) {
        int r = 0;
        while (mk[r]) r++;                    // first unmasked rank (<= 600)
        g_mxu[k] = (unsigned)(buf[r] >> 32);  // exact post-mask row max key
    }
}

// ---------------- sum pass: write A_raw, accumulate exp partial sums ----------------
__global__ void __launch_bounds__(256) sumexp_k(
    const float* __restrict__ At, float* __restrict__ outA)
{
    const int k = blockIdx.y;
    const float mx = u2f(g_mxu[k]);
    const float* row = At + (size_t)k * NPATCH;
    const int base = blockIdx.x * 2500;
    float sm = 0.f;
    for (int j = base + threadIdx.x; j < base + 2500; j += 256) {
        float v = row[j];
        outA[(size_t)k * NPATCH + j] = v;
        sm += expf(v - mx);
    }
    __shared__ float sred[8];
    #pragma unroll
    for (int o = 16; o; o >>= 1) sm += __shfl_xor_sync(0xffffffffu, sm, o);
    if ((threadIdx.x & 31) == 0) sred[threadIdx.x >> 5] = sm;
    __syncthreads();
    if (threadIdx.x == 0) {
        float s = 0.f;
        for (int w = 0; w < 8; w++) s += sred[w];
        g_psum[k][blockIdx.x] = s;
    }
}

// ---------------- M_raw = exp(At - mx) @ x (normalization deferred) ----------------
#define PCHUNK 400
__global__ void __launch_bounds__(128) pool_k(
    const float* __restrict__ At, const float* __restrict__ x, float* __restrict__ Mout)
{
    const int h = blockIdx.x * 128 + threadIdx.x;
    const int n0 = blockIdx.y * PCHUNK;
    float mx[KHEADS];
    #pragma unroll
    for (int kk = 0; kk < KHEADS; kk++) mx[kk] = u2f(g_mxu[kk]);
    float acc[KHEADS] = {0.f, 0.f, 0.f, 0.f, 0.f};
    for (int n = n0; n < n0 + PCHUNK; n++) {
        float xv = x[(size_t)n * HDIM + h];
        #pragma unroll
        for (int kk = 0; kk < KHEADS; kk++) {
            float e = expf(At[(size_t)kk * NPATCH + n] - mx[kk]);
            acc[kk] = fmaf(e, xv, acc[kk]);
        }
    }
    #pragma unroll
    for (int kk = 0; kk < KHEADS; kk++) atomicAdd(&Mout[kk * HDIM + h], acc[kk]);
}

// ---------------- final heads (applies deferred 1/s_k) ----------------
__global__ void __launch_bounds__(512) final_k(
    const float* __restrict__ Mbuf,
    const float* __restrict__ Wcls, const float* __restrict__ bcls,
    const float* __restrict__ Wbag, const float* __restrict__ bbag,
    float* __restrict__ out)
{
    const int tid = threadIdx.x;
    float inv[KHEADS];
    #pragma unroll
    for (int k = 0; k < KHEADS; k++) {
        float s = 0.f;
        for (int w = 0; w < 40; w++) s += g_psum[k][w];   // fixed order
        inv[k] = 1.f / s;
    }
    float m[KHEADS];
    #pragma unroll
    for (int k = 0; k < KHEADS; k++) m[k] = Mbuf[k * HDIM + tid] * inv[k];
    float bagf = 0.2f * (m[0] + m[1] + m[2] + m[3] + m[4]);
    float v[12];
    #pragma unroll
    for (int k = 0; k < KHEADS; k++)
        #pragma unroll
        for (int c = 0; c < NCLS; c++)
            v[k * 2 + c] = m[k] * Wcls[(size_t)k * HDIM * NCLS + tid * NCLS + c];
    v[10] = bagf * Wbag[tid * NCLS + 0];
    v[11] = bagf * Wbag[tid * NCLS + 1];

    __shared__ float red[16][12];
    #pragma unroll
    for (int e = 0; e < 12; e++)
        #pragma unroll
        for (int o = 16; o; o >>= 1) v[e] += __shfl_xor_sync(0xffffffffu, v[e], o);
    if ((tid & 31) == 0)
        for (int e = 0; e < 12; e++) red[tid >> 5][e] = v[e];
    __syncthreads();
    if (tid == 0) {
        float s[12];
        for (int e = 0; e < 12; e++) { s[e] = 0.f; for (int w = 0; w < 16; w++) s[e] += red[w][e]; }
        for (int k = 0; k < KHEADS; k++)
            for (int c = 0; c < NCLS; c++)
                out[k * 2 + c] = s[k * 2 + c] + bcls[k * 2 + c];
        out[10] = s[10] + bbag[0];
        out[11] = s[11] + bbag[1];
    }
}

// ---------------- launch ----------------
extern "C" void kernel_launch(void* const* d_in, const int* in_sizes, int n_in,
                              void* d_out, int out_size)
{
    const float* h    = (const float*)d_in[0];
    const int*   rsel = (const int*)  d_in[1];
    const float* W1   = (const float*)d_in[2];
    const float* b1   = (const float*)d_in[3];
    const float* Wa   = (const float*)d_in[4];
    const float* ba   = (const float*)d_in[5];
    const float* Wb   = (const float*)d_in[6];
    const float* bb   = (const float*)d_in[7];
    const float* Wc   = (const float*)d_in[8];
    const float* bc   = (const float*)d_in[9];
    const float* Wcls = (const float*)d_in[10];
    const float* bcls = (const float*)d_in[11];
    const float* Wbag = (const float*)d_in[12];
    const float* bbag = (const float*)d_in[13];
    float* out = (float*)d_out;

    float *px, *pag, *pAt, *pM, *pWab;
    cudaGetSymbolAddress((void**)&px,   g_x);
    cudaGetSymbolAddress((void**)&pag,  g_ag);
    cudaGetSymbolAddress((void**)&pAt,  g_At);
    cudaGetSymbolAddress((void**)&pM,   g_M);
    cudaGetSymbolAddress((void**)&pWab, g_Wab);

    cudaFuncSetAttribute((const void*)f2gemm<1024, 0>,
                         cudaFuncAttributeMaxDynamicSharedMemorySize, GSM_BYTES);
    cudaFuncSetAttribute((const void*)f2gemm<512, 1>,
                         cudaFuncAttributeMaxDynamicSharedMemorySize, GSM_BYTES);
    cudaFuncSetAttribute((const void*)topk_mask2_k,
                         cudaFuncAttributeMaxDynamicSharedMemorySize, 8192 * 8 + 1024);

    prep_wab<<<512, 256>>>(Wa, Wb);

    const int MBLK = (NPATCH + 127) / 128;   // 782
    f2gemm<1024, 0><<<dim3(4, MBLK), 256, GSM_BYTES>>>(h,  W1,   b1, nullptr, px,  NPATCH);
    f2gemm<512,  1><<<dim3(4, MBLK), 256, GSM_BYTES>>>(px, pWab, ba, bb,      pag, NPATCH);

    attn_scores_k<<<(NPATCH + 255) / 256, 256>>>(pag, Wc, bc, pAt);

    topk_pivot_k<<<KHEADS, 1024>>>(pAt, pM);
    topk_gather_k<<<dim3(40, KHEADS), 256>>>(pAt);
    topk_mask2_k<<<KHEADS, 1024, 8192 * 8 + 1024>>>(pAt, rsel);

    sumexp_k<<<dim3(40, KHEADS), 256>>>(pAt, out + 12);

    pool_k<<<dim3(HDIM / 128, NPATCH / PCHUNK), 128>>>(pAt, px, pM);
    final_k<<<1, HDIM>>>(pM, Wcls, bcls, Wbag, bbag, out);
}

// round 14
// speedup vs baseline: 1.0400x; 1.0400x over previous
#include <cuda_runtime.h>
#include <math.h>
#include <stdint.h>

#define NPATCH 100000
#define LDIM   1024
#define HDIM   512
#define DDIM   256
#define KHEADS 5
#define NCLS   2
#define MTOP   1000
#define MDROP  600
#define NEGV   (-1.0e9f)
#define CANDC  8192

// ---------------- scratch ----------------
__device__ float g_x [(size_t)NPATCH * HDIM];
__device__ float g_ag[(size_t)NPATCH * DDIM];
__device__ float g_At[(size_t)KHEADS * NPATCH];
__device__ float g_Asm[(size_t)KHEADS * NPATCH];
__device__ float g_M [KHEADS * HDIM];
__device__ float g_Wab[(size_t)512 * 512];
__device__ unsigned g_pivot[KHEADS];
__device__ unsigned g_ccnt[KHEADS];
__device__ unsigned g_mxu[KHEADS];
__device__ float g_psum[KHEADS][40];
__device__ unsigned long long g_cand[(size_t)KHEADS * CANDC];

// ---------------- helpers ----------------
__device__ __forceinline__ unsigned long long pk2(float lo, float hi) {
    unsigned long long r;
    asm("mov.b64 %0, {%1, %2};" : "=l"(r) : "f"(lo), "f"(hi));
    return r;
}
__device__ __forceinline__ void ffma2(unsigned long long& d, unsigned long long a,
                                      unsigned long long b) {
    asm("fma.rn.f32x2 %0, %1, %2, %0;" : "+l"(d) : "l"(a), "l"(b));
}
__device__ __forceinline__ float2 upk2(unsigned long long v) {
    float2 r;
    asm("mov.b64 {%0, %1}, %2;" : "=f"(r.x), "=f"(r.y) : "l"(v));
    return r;
}
__device__ __forceinline__ uint32_t smem_u32(const void* p) {
    uint32_t a;
    asm("{ .reg .u64 t; cvta.to.shared.u64 t, %1; cvt.u32.u64 %0, t; }" : "=r"(a) : "l"(p));
    return a;
}
__device__ __forceinline__ void cp16(uint32_t dst, const void* src) {
    asm volatile("cp.async.cg.shared.global [%0], [%1], 16;" :: "r"(dst), "l"(src));
}
#define CP_COMMIT() asm volatile("cp.async.commit_group;" ::: "memory")
#define CP_WAIT0()  asm volatile("cp.async.wait_group 0;" ::: "memory")

__device__ __forceinline__ unsigned f2u(float f) {
    unsigned u = __float_as_uint(f);
    return (u & 0x80000000u) ? ~u : (u | 0x80000000u);
}
__device__ __forceinline__ float u2f(unsigned u) {
    unsigned b = (u & 0x80000000u) ? (u & 0x7FFFFFFFu) : ~u;
    return __uint_as_float(b);
}

// ---------------- prep kernels ----------------
__global__ void prep_wab(const float* __restrict__ Wa, const float* __restrict__ Wb) {
    int idx = blockIdx.x * 256 + threadIdx.x;
    if (idx >= 512 * 256) return;
    int k = idx >> 8, d = idx & 255;
    g_Wab[(size_t)k * 512 + 2 * d]     = Wa[(size_t)k * 256 + d];
    g_Wab[(size_t)k * 512 + 2 * d + 1] = Wb[(size_t)k * 256 + d];
}

// ============ FFMA2 SGEMM: k-tile 32, dynamic smem, 2 CTA/SM (FROZEN) ============
#define GSM_FLOATS (2 * 8192)
#define GSM_BYTES  (GSM_FLOATS * 4)

template<int KTOT, int EPI>
__global__ void __launch_bounds__(256, 2) f2gemm(
    const float* __restrict__ A, const float* __restrict__ B,
    const float* __restrict__ bias0, const float* __restrict__ bias1,
    float* __restrict__ Out, int Mrows)
{
    extern __shared__ float smf[];           // [2][ A:32x128 | B:32x128 ]
    constexpr int NT = KTOT / 32;
    const int tid = threadIdx.x;
    const int m0 = blockIdx.y * 128;
    const int n0 = blockIdx.x * 128;
    const int tm = tid >> 4, tn = tid & 15;
    const int ar = tid >> 1, ak = (tid & 1) << 2;
    const int bk = tid >> 5;                 // 0..7
    const int bn = (tid & 31) << 2;
    const bool aval = (m0 + ar) < Mrows;
    const float* Ap = A + (size_t)(m0 + ar) * KTOT + ak;
    const float* Bp = B + (size_t)bk * 512 + n0 + bn;

    float* As0 = smf;            float* Bs0 = smf + 4096;
    float* As1 = smf + 8192;     float* Bs1 = smf + 12288;
    uint32_t bu0 = smem_u32(Bs0 + bk * 128 + bn);
    uint32_t bu1 = smem_u32(Bs1 + bk * 128 + bn);

    unsigned long long acc[8][4];
    #pragma unroll
    for (int i = 0; i < 8; i++)
        #pragma unroll
        for (int p = 0; p < 4; p++) acc[i][p] = 0ULL;

    // prologue: stage 0
    {
        #pragma unroll
        for (int o = 0; o < 4; o++) {
            float4 a = aval ? *(const float4*)(Ap + o * 8) : make_float4(0.f, 0.f, 0.f, 0.f);
            As0[(ak + o * 8 + 0) * 128 + ar] = a.x;
            As0[(ak + o * 8 + 1) * 128 + ar] = a.y;
            As0[(ak + o * 8 + 2) * 128 + ar] = a.z;
            As0[(ak + o * 8 + 3) * 128 + ar] = a.w;
            cp16(bu0 + o * 8 * 128 * 4, Bp + (size_t)o * 8 * 512);
        }
        CP_COMMIT();
    }

    for (int kt = 0; kt < NT; kt++) {
        const int buf = kt & 1;
        float* Asc = buf ? As1 : As0;
        float* Bsc = buf ? Bs1 : Bs0;
        CP_WAIT0();
        __syncthreads();
        const bool nxt = (kt + 1) < NT;
        float4 avn[4];
        if (nxt) {
            #pragma unroll
            for (int o = 0; o < 4; o++) {
                avn[o] = aval ? *(const float4*)(Ap + (size_t)(kt + 1) * 32 + o * 8)
                              : make_float4(0.f, 0.f, 0.f, 0.f);
                cp16((buf ? bu0 : bu1) + o * 8 * 128 * 4,
                     Bp + ((size_t)(kt + 1) * 32 + o * 8) * 512);
            }
            CP_COMMIT();
        }
        #pragma unroll
        for (int kk = 0; kk < 32; kk++) {
            float ra[8], rb[8];
            *(float4*)&ra[0] = *(const float4*)&Asc[kk * 128 + (tm << 2)];
            *(float4*)&ra[4] = *(const float4*)&Asc[kk * 128 + 64 + (tm << 2)];
            *(float4*)&rb[0] = *(const float4*)&Bsc[kk * 128 + (tn << 2)];
            *(float4*)&rb[4] = *(const float4*)&Bsc[kk * 128 + 64 + (tn << 2)];
            unsigned long long ap[8], bp[4];
            #pragma unroll
            for (int i = 0; i < 8; i++) ap[i] = pk2(ra[i], ra[i]);
            bp[0] = pk2(rb[0], rb[1]); bp[1] = pk2(rb[2], rb[3]);
            bp[2] = pk2(rb[4], rb[5]); bp[3] = pk2(rb[6], rb[7]);
            #pragma unroll
            for (int i = 0; i < 8; i++)
                #pragma unroll
                for (int p = 0; p < 4; p++) ffma2(acc[i][p], ap[i], bp[p]);
        }
        if (nxt) {
            float* Asn = buf ? As0 : As1;
            #pragma unroll
            for (int o = 0; o < 4; o++) {
                Asn[(ak + o * 8 + 0) * 128 + ar] = avn[o].x;
                Asn[(ak + o * 8 + 1) * 128 + ar] = avn[o].y;
                Asn[(ak + o * 8 + 2) * 128 + ar] = avn[o].z;
                Asn[(ak + o * 8 + 3) * 128 + ar] = avn[o].w;
            }
        }
    }

    // ---------------- epilogue ----------------
    #pragma unroll
    for (int i = 0; i < 8; i++) {
        const int m = m0 + ((i < 4) ? (tm << 2) + i : 64 + (tm << 2) + i - 4);
        if (m >= Mrows) continue;
        #pragma unroll
        for (int p = 0; p < 4; p++) {
            float2 v = upk2(acc[i][p]);
            const int nl = (p < 2) ? (tn << 2) + 2 * p : 64 + (tn << 2) + 2 * (p - 2);
            const int n = n0 + nl;
            if (EPI == 0) {
                v.x = fmaxf(v.x + bias0[n], 0.f);
                v.y = fmaxf(v.y + bias0[n + 1], 0.f);
                *(float2*)&Out[(size_t)m * 512 + n] = v;
            } else {
                const int d = n >> 1;
                float a = tanhf(v.x + bias0[d]);
                float g = 1.f / (1.f + expf(-(v.y + bias1[d])));
                Out[(size_t)m * 256 + d] = a * g;
            }
        }
    }
}

// ---------------- A = ag @ Wc + bc (sequential d order -- rank-stable, FROZEN) ----------------
__global__ void __launch_bounds__(256) attn_scores_k(
    const float* __restrict__ ag, const float* __restrict__ Wc,
    const float* __restrict__ bc, float* __restrict__ At)
{
    __shared__ float sW[DDIM * KHEADS];
    __shared__ float sb[KHEADS];
    for (int i = threadIdx.x; i < DDIM * KHEADS; i += blockDim.x) sW[i] = Wc[i];
    if (threadIdx.x < KHEADS) sb[threadIdx.x] = bc[threadIdx.x];
    __syncthreads();
    int n = blockIdx.x * blockDim.x + threadIdx.x;
    if (n >= NPATCH) return;
    float acc[KHEADS];
    #pragma unroll
    for (int k = 0; k < KHEADS; k++) acc[k] = sb[k];
    const float4* r = (const float4*)(ag + (size_t)n * DDIM);
    #pragma unroll 4
    for (int q = 0; q < DDIM / 4; q++) {
        float4 v = r[q];
        int d = q * 4;
        #pragma unroll
        for (int k = 0; k < KHEADS; k++) {
            acc[k] = fmaf(v.x, sW[(d + 0) * KHEADS + k], acc[k]);
            acc[k] = fmaf(v.y, sW[(d + 1) * KHEADS + k], acc[k]);
            acc[k] = fmaf(v.z, sW[(d + 2) * KHEADS + k], acc[k]);
            acc[k] = fmaf(v.w, sW[(d + 3) * KHEADS + k], acc[k]);
        }
    }
    #pragma unroll
    for (int k = 0; k < KHEADS; k++) At[(size_t)k * NPATCH + n] = acc[k];
}

// ---------------- top-k stage 1: deterministic sample pivot (+ zero g_M) ----------------
__global__ void __launch_bounds__(1024) topk_pivot_k(const float* __restrict__ At,
                                                     float* __restrict__ Mout) {
    const int k = blockIdx.x, tid = threadIdx.x;
    __shared__ unsigned sk[2048];
    if (tid < HDIM) Mout[k * HDIM + tid] = 0.f;
    for (int j = tid; j < 2048; j += 1024)
        sk[j] = (j < 1536) ? f2u(At[(size_t)k * NPATCH + j * 65]) : 0u;
    __syncthreads();
    for (int kk = 2; kk <= 2048; kk <<= 1) {
        for (int j = kk >> 1; j > 0; j >>= 1) {
            int i = ((tid & ~(j - 1)) << 1) | (tid & (j - 1));
            int l = i | j;
            unsigned a = sk[i], b = sk[l];
            bool asc = (i & kk) != 0;
            if (asc ? (a > b) : (a < b)) { sk[i] = b; sk[l] = a; }
            __syncthreads();
        }
    }
    if (tid == 0) {
        g_pivot[k] = sk[63];
        g_ccnt[k] = 0;
    }
}

// ---------------- top-k stage 2: grid-wide candidate gather ----------------
__global__ void __launch_bounds__(256) topk_gather_k(const float* __restrict__ At) {
    const int k = blockIdx.y;
    const unsigned pivot = g_pivot[k];
    const float* row = At + (size_t)k * NPATCH;
    const int base = blockIdx.x * 2500;
    for (int j = base + threadIdx.x; j < base + 2500; j += 256) {
        unsigned u = f2u(row[j]);
        if (u >= pivot) {
            unsigned p = atomicAdd(&g_ccnt[k], 1u);
            if (p < CANDC)
                g_cand[(size_t)k * CANDC + p] =
                    ((unsigned long long)u << 32) | (unsigned)(~(unsigned)j);
        }
    }
}

// ---- top-k stage 3: sort + mask + extract post-mask row max (replaces smax1) ----
__global__ void __launch_bounds__(1024) topk_mask2_k(
    float* __restrict__ At, const int* __restrict__ rand_sel)
{
    extern __shared__ unsigned long long buf[];   // 8192 + flags
    unsigned char* mk = (unsigned char*)(buf + 8192);  // 1024 flags
    const int k = blockIdx.x, tid = threadIdx.x;
    unsigned cnt = g_ccnt[k]; if (cnt > CANDC) cnt = CANDC;
    for (int i = tid; i < 8192; i += 1024)
        buf[i] = (i < (int)cnt) ? g_cand[(size_t)k * CANDC + i] : 0ULL;
    if (tid < 1024) mk[tid] = 0;
    __syncthreads();
    for (int kk = 2; kk <= 8192; kk <<= 1) {
        for (int j = kk >> 1; j > 0; j >>= 1) {
            for (int w = tid; w < 4096; w += 1024) {
                int i = ((w & ~(j - 1)) << 1) | (w & (j - 1));
                int l = i | j;
                unsigned long long a = buf[i], b = buf[l];
                bool asc = (i & kk) != 0;
                if (asc ? (a > b) : (a < b)) { buf[i] = b; buf[l] = a; }
            }
            __syncthreads();
        }
    }
    float* row = At + (size_t)k * NPATCH;
    for (int j = tid; j < MDROP; j += 1024) {
        int rs = rand_sel[k * MDROP + j];
        mk[rs] = 1;
        int idx = (int)(~(unsigned)(buf[rs] & 0xFFFFFFFFULL));
        row[idx] = NEGV;
    }
    __syncthreads();
    if (tid == 0) {
        int r = 0;
        while (mk[r]) r++;                    // first unmasked rank (<= 600)
        g_mxu[k] = (unsigned)(buf[r] >> 32);  // exact post-mask row max key
    }
}

// ---- sum pass: write A_raw + Asm = exp(v-mx) (unnormalized) + partial sums ----
__global__ void __launch_bounds__(256) sumexp_k(
    const float* __restrict__ At, float* __restrict__ Asm, float* __restrict__ outA)
{
    const int k = blockIdx.y;
    const float mx = u2f(g_mxu[k]);
    const float* row = At + (size_t)k * NPATCH;
    const int base = blockIdx.x * 2500;
    float sm = 0.f;
    for (int j = base + threadIdx.x; j < base + 2500; j += 256) {
        float v = row[j];
        outA[(size_t)k * NPATCH + j] = v;
        float e = expf(v - mx);
        Asm[(size_t)k * NPATCH + j] = e;
        sm += e;
    }
    __shared__ float sred[8];
    #pragma unroll
    for (int o = 16; o; o >>= 1) sm += __shfl_xor_sync(0xffffffffu, sm, o);
    if ((threadIdx.x & 31) == 0) sred[threadIdx.x >> 5] = sm;
    __syncthreads();
    if (threadIdx.x == 0) {
        float s = 0.f;
        for (int w = 0; w < 8; w++) s += sred[w];
        g_psum[k][blockIdx.x] = s;
    }
}

// ---------------- M_raw = Asm_unnorm @ x (normalization deferred) ----------------
#define PCHUNK 400
__global__ void __launch_bounds__(128) pool_k(
    const float* __restrict__ Asm, const float* __restrict__ x, float* __restrict__ Mout)
{
    const int h = blockIdx.x * 128 + threadIdx.x;
    const int n0 = blockIdx.y * PCHUNK;
    float acc[KHEADS] = {0.f, 0.f, 0.f, 0.f, 0.f};
    for (int n = n0; n < n0 + PCHUNK; n++) {
        float xv = x[(size_t)n * HDIM + h];
        #pragma unroll
        for (int kk = 0; kk < KHEADS; kk++)
            acc[kk] = fmaf(Asm[(size_t)kk * NPATCH + n], xv, acc[kk]);
    }
    #pragma unroll
    for (int kk = 0; kk < KHEADS; kk++) atomicAdd(&Mout[kk * HDIM + h], acc[kk]);
}

// ---------------- final heads (applies deferred 1/s_k) ----------------
__global__ void __launch_bounds__(512) final_k(
    const float* __restrict__ Mbuf,
    const float* __restrict__ Wcls, const float* __restrict__ bcls,
    const float* __restrict__ Wbag, const float* __restrict__ bbag,
    float* __restrict__ out)
{
    const int tid = threadIdx.x;
    float inv[KHEADS];
    #pragma unroll
    for (int k = 0; k < KHEADS; k++) {
        float s = 0.f;
        for (int w = 0; w < 40; w++) s += g_psum[k][w];   // fixed order
        inv[k] = 1.f / s;
    }
    float m[KHEADS];
    #pragma unroll
    for (int k = 0; k < KHEADS; k++) m[k] = Mbuf[k * HDIM + tid] * inv[k];
    float bagf = 0.2f * (m[0] + m[1] + m[2] + m[3] + m[4]);
    float v[12];
    #pragma unroll
    for (int k = 0; k < KHEADS; k++)
        #pragma unroll
        for (int c = 0; c < NCLS; c++)
            v[k * 2 + c] = m[k] * Wcls[(size_t)k * HDIM * NCLS + tid * NCLS + c];
    v[10] = bagf * Wbag[tid * NCLS + 0];
    v[11] = bagf * Wbag[tid * NCLS + 1];

    __shared__ float red[16][12];
    #pragma unroll
    for (int e = 0; e < 12; e++)
        #pragma unroll
        for (int o = 16; o; o >>= 1) v[e] += __shfl_xor_sync(0xffffffffu, v[e], o);
    if ((tid & 31) == 0)
        for (int e = 0; e < 12; e++) red[tid >> 5][e] = v[e];
    __syncthreads();
    if (tid == 0) {
        float s[12];
        for (int e = 0; e < 12; e++) { s[e] = 0.f; for (int w = 0; w < 16; w++) s[e] += red[w][e]; }
        for (int k = 0; k < KHEADS; k++)
            for (int c = 0; c < NCLS; c++)
                out[k * 2 + c] = s[k * 2 + c] + bcls[k * 2 + c];
        out[10] = s[10] + bbag[0];
        out[11] = s[11] + bbag[1];
    }
}

// ---------------- launch ----------------
extern "C" void kernel_launch(void* const* d_in, const int* in_sizes, int n_in,
                              void* d_out, int out_size)
{
    const float* h    = (const float*)d_in[0];
    const int*   rsel = (const int*)  d_in[1];
    const float* W1   = (const float*)d_in[2];
    const float* b1   = (const float*)d_in[3];
    const float* Wa   = (const float*)d_in[4];
    const float* ba   = (const float*)d_in[5];
    const float* Wb   = (const float*)d_in[6];
    const float* bb   = (const float*)d_in[7];
    const float* Wc   = (const float*)d_in[8];
    const float* bc   = (const float*)d_in[9];
    const float* Wcls = (const float*)d_in[10];
    const float* bcls = (const float*)d_in[11];
    const float* Wbag = (const float*)d_in[12];
    const float* bbag = (const float*)d_in[13];
    float* out = (float*)d_out;

    float *px, *pag, *pAt, *pAsm, *pM, *pWab;
    cudaGetSymbolAddress((void**)&px,   g_x);
    cudaGetSymbolAddress((void**)&pag,  g_ag);
    cudaGetSymbolAddress((void**)&pAt,  g_At);
    cudaGetSymbolAddress((void**)&pAsm, g_Asm);
    cudaGetSymbolAddress((void**)&pM,   g_M);
    cudaGetSymbolAddress((void**)&pWab, g_Wab);

    cudaFuncSetAttribute((const void*)f2gemm<1024, 0>,
                         cudaFuncAttributeMaxDynamicSharedMemorySize, GSM_BYTES);
    cudaFuncSetAttribute((const void*)f2gemm<512, 1>,
                         cudaFuncAttributeMaxDynamicSharedMemorySize, GSM_BYTES);
    cudaFuncSetAttribute((const void*)topk_mask2_k,
                         cudaFuncAttributeMaxDynamicSharedMemorySize, 8192 * 8 + 1024);

    prep_wab<<<512, 256>>>(Wa, Wb);

    const int MBLK = (NPATCH + 127) / 128;   // 782
    f2gemm<1024, 0><<<dim3(4, MBLK), 256, GSM_BYTES>>>(h,  W1,   b1, nullptr, px,  NPATCH);
    f2gemm<512,  1><<<dim3(4, MBLK), 256, GSM_BYTES>>>(px, pWab, ba, bb,      pag, NPATCH);

    attn_scores_k<<<(NPATCH + 255) / 256, 256>>>(pag, Wc, bc, pAt);

    topk_pivot_k<<<KHEADS, 1024>>>(pAt, pM);
    topk_gather_k<<<dim3(40, KHEADS), 256>>>(pAt);
    topk_mask2_k<<<KHEADS, 1024, 8192 * 8 + 1024>>>(pAt, rsel);

    sumexp_k<<<dim3(40, KHEADS), 256>>>(pAt, pAsm, out + 12);

    pool_k<<<dim3(HDIM / 128, NPATCH / PCHUNK), 128>>>(pAsm, px, pM);
    final_k<<<1, HDIM>>>(pM, Wcls, bcls, Wbag, bbag, out);
}

// round 15
// speedup vs baseline: 1.0407x; 1.0006x over previous
#include <cuda_runtime.h>
#include <math.h>
#include <stdint.h>

#define NPATCH 100000
#define LDIM   1024
#define HDIM   512
#define DDIM   256
#define KHEADS 5
#define NCLS   2
#define MTOP   1000
#define MDROP  600
#define NEGV   (-1.0e9f)
#define CANDC  8192

// ---------------- scratch ----------------
__device__ float g_x [(size_t)NPATCH * HDIM];
__device__ float g_ag[(size_t)NPATCH * DDIM];
__device__ float g_At[(size_t)KHEADS * NPATCH];
__device__ float g_Asm[(size_t)KHEADS * NPATCH];
__device__ float g_M [KHEADS * HDIM];
__device__ float g_Wab[(size_t)512 * 512];
__device__ unsigned g_pivot[KHEADS];
__device__ unsigned g_ccnt[KHEADS];
__device__ unsigned g_mxu[KHEADS];
__device__ float g_psum[KHEADS][40];
__device__ unsigned long long g_cand[(size_t)KHEADS * CANDC];

// ---------------- helpers ----------------
__device__ __forceinline__ unsigned long long pk2(float lo, float hi) {
    unsigned long long r;
    asm("mov.b64 %0, {%1, %2};" : "=l"(r) : "f"(lo), "f"(hi));
    return r;
}
__device__ __forceinline__ void ffma2(unsigned long long& d, unsigned long long a,
                                      unsigned long long b) {
    asm("fma.rn.f32x2 %0, %1, %2, %0;" : "+l"(d) : "l"(a), "l"(b));
}
__device__ __forceinline__ float2 upk2(unsigned long long v) {
    float2 r;
    asm("mov.b64 {%0, %1}, %2;" : "=f"(r.x), "=f"(r.y) : "l"(v));
    return r;
}
__device__ __forceinline__ uint32_t smem_u32(const void* p) {
    uint32_t a;
    asm("{ .reg .u64 t; cvta.to.shared.u64 t, %1; cvt.u32.u64 %0, t; }" : "=r"(a) : "l"(p));
    return a;
}
__device__ __forceinline__ void cp16(uint32_t dst, const void* src) {
    asm volatile("cp.async.cg.shared.global [%0], [%1], 16;" :: "r"(dst), "l"(src));
}
#define CP_COMMIT() asm volatile("cp.async.commit_group;" ::: "memory")
#define CP_WAIT0()  asm volatile("cp.async.wait_group 0;" ::: "memory")

__device__ __forceinline__ unsigned f2u(float f) {
    unsigned u = __float_as_uint(f);
    return (u & 0x80000000u) ? ~u : (u | 0x80000000u);
}
__device__ __forceinline__ float u2f(unsigned u) {
    unsigned b = (u & 0x80000000u) ? (u & 0x7FFFFFFFu) : ~u;
    return __uint_as_float(b);
}

// ---------------- prep kernels ----------------
__global__ void prep_wab(const float* __restrict__ Wa, const float* __restrict__ Wb) {
    int idx = blockIdx.x * 256 + threadIdx.x;
    if (idx >= 512 * 256) return;
    int k = idx >> 8, d = idx & 255;
    g_Wab[(size_t)k * 512 + 2 * d]     = Wa[(size_t)k * 256 + d];
    g_Wab[(size_t)k * 512 + 2 * d + 1] = Wb[(size_t)k * 256 + d];
}

// ============ GEMM1: FFMA2, CTA 128m x 256n, 8x16/thread, k-tile 32, 1 CTA/SM ============
// k-ascending accumulation per output: bitwise-identical x to the 8x8 version.
// x = relu(acc + bias0) -> Out[m][512]
#define G1SM_FLOATS (2 * (32 * 128 + 32 * 256))
#define G1SM_BYTES  (G1SM_FLOATS * 4)

__global__ void __launch_bounds__(256) f2gemm1w(
    const float* __restrict__ A, const float* __restrict__ B,
    const float* __restrict__ bias0, float* __restrict__ Out, int Mrows)
{
    constexpr int KTOT = 1024;
    constexpr int NT = KTOT / 32;
    extern __shared__ float smf[];
    const int tid = threadIdx.x;
    const int m0 = blockIdx.y * 128;
    const int n0 = blockIdx.x * 256;
    const int tm = tid >> 4, tn = tid & 15;
    const int ar = tid >> 1, ak = (tid & 1) << 2;       // A staging (as before)
    const int bk2 = tid >> 6;                            // 0..3
    const int bn2 = (tid & 63) << 2;                     // 0..252
    const bool aval = (m0 + ar) < Mrows;
    const float* Ap = A + (size_t)(m0 + ar) * KTOT + ak;
    const float* Bp = B + (size_t)bk2 * 512 + n0 + bn2;

    float* As0 = smf;                       // 32x128
    float* Bs0 = smf + 4096;                // 32x256
    float* As1 = smf + 12288;
    float* Bs1 = smf + 16384;
    uint32_t bu0 = smem_u32(Bs0 + bk2 * 256 + bn2);
    uint32_t bu1 = smem_u32(Bs1 + bk2 * 256 + bn2);

    unsigned long long acc[8][8];
    #pragma unroll
    for (int i = 0; i < 8; i++)
        #pragma unroll
        for (int p = 0; p < 8; p++) acc[i][p] = 0ULL;

    // prologue: stage 0
    {
        #pragma unroll
        for (int o = 0; o < 4; o++) {
            float4 a = aval ? *(const float4*)(Ap + o * 8) : make_float4(0.f, 0.f, 0.f, 0.f);
            As0[(ak + o * 8 + 0) * 128 + ar] = a.x;
            As0[(ak + o * 8 + 1) * 128 + ar] = a.y;
            As0[(ak + o * 8 + 2) * 128 + ar] = a.z;
            As0[(ak + o * 8 + 3) * 128 + ar] = a.w;
        }
        #pragma unroll
        for (int o = 0; o < 8; o++)
            cp16(bu0 + o * 4 * 256 * 4, Bp + (size_t)o * 4 * 512);
        CP_COMMIT();
    }

    for (int kt = 0; kt < NT; kt++) {
        const int buf = kt & 1;
        float* Asc = buf ? As1 : As0;
        float* Bsc = buf ? Bs1 : Bs0;
        CP_WAIT0();
        __syncthreads();
        const bool nxt = (kt + 1) < NT;
        float4 avn[4];
        if (nxt) {
            #pragma unroll
            for (int o = 0; o < 4; o++)
                avn[o] = aval ? *(const float4*)(Ap + (size_t)(kt + 1) * 32 + o * 8)
                              : make_float4(0.f, 0.f, 0.f, 0.f);
            #pragma unroll
            for (int o = 0; o < 8; o++)
                cp16((buf ? bu0 : bu1) + o * 4 * 256 * 4,
                     Bp + ((size_t)(kt + 1) * 32 + o * 4) * 512);
            CP_COMMIT();
        }
        #pragma unroll
        for (int kk = 0; kk < 32; kk++) {
            float ra[8], rb[16];
            *(float4*)&ra[0]  = *(const float4*)&Asc[kk * 128 + (tm << 2)];
            *(float4*)&ra[4]  = *(const float4*)&Asc[kk * 128 + 64 + (tm << 2)];
            *(float4*)&rb[0]  = *(const float4*)&Bsc[kk * 256 + (tn << 2)];
            *(float4*)&rb[4]  = *(const float4*)&Bsc[kk * 256 + 64 + (tn << 2)];
            *(float4*)&rb[8]  = *(const float4*)&Bsc[kk * 256 + 128 + (tn << 2)];
            *(float4*)&rb[12] = *(const float4*)&Bsc[kk * 256 + 192 + (tn << 2)];
            unsigned long long ap[8], bp[8];
            #pragma unroll
            for (int i = 0; i < 8; i++) ap[i] = pk2(ra[i], ra[i]);
            #pragma unroll
            for (int p = 0; p < 8; p++) bp[p] = pk2(rb[2 * p], rb[2 * p + 1]);
            #pragma unroll
            for (int i = 0; i < 8; i++)
                #pragma unroll
                for (int p = 0; p < 8; p++) ffma2(acc[i][p], ap[i], bp[p]);
        }
        if (nxt) {
            float* Asn = buf ? As0 : As1;
            #pragma unroll
            for (int o = 0; o < 4; o++) {
                Asn[(ak + o * 8 + 0) * 128 + ar] = avn[o].x;
                Asn[(ak + o * 8 + 1) * 128 + ar] = avn[o].y;
                Asn[(ak + o * 8 + 2) * 128 + ar] = avn[o].z;
                Asn[(ak + o * 8 + 3) * 128 + ar] = avn[o].w;
            }
        }
    }

    // epilogue: relu(acc + bias0)
    #pragma unroll
    for (int i = 0; i < 8; i++) {
        const int m = m0 + ((i < 4) ? (tm << 2) + i : 64 + (tm << 2) + i - 4);
        if (m >= Mrows) continue;
        #pragma unroll
        for (int p = 0; p < 8; p++) {
            float2 v = upk2(acc[i][p]);
            const int nl = (p >> 1) * 64 + (tn << 2) + 2 * (p & 1);
            const int n = n0 + nl;
            v.x = fmaxf(v.x + bias0[n], 0.f);
            v.y = fmaxf(v.y + bias0[n + 1], 0.f);
            *(float2*)&Out[(size_t)m * 512 + n] = v;
        }
    }
}

// ============ GEMM2: FFMA2 SGEMM k-tile 32, 2 CTA/SM (R14 verbatim, FROZEN) ============
#define GSM_FLOATS (2 * 8192)
#define GSM_BYTES  (GSM_FLOATS * 4)

__global__ void __launch_bounds__(256, 2) f2gemm2(
    const float* __restrict__ A, const float* __restrict__ B,
    const float* __restrict__ bias0, const float* __restrict__ bias1,
    float* __restrict__ Out, int Mrows)
{
    constexpr int KTOT = 512;
    extern __shared__ float smf[];
    constexpr int NT = KTOT / 32;
    const int tid = threadIdx.x;
    const int m0 = blockIdx.y * 128;
    const int n0 = blockIdx.x * 128;
    const int tm = tid >> 4, tn = tid & 15;
    const int ar = tid >> 1, ak = (tid & 1) << 2;
    const int bk = tid >> 5;
    const int bn = (tid & 31) << 2;
    const bool aval = (m0 + ar) < Mrows;
    const float* Ap = A + (size_t)(m0 + ar) * KTOT + ak;
    const float* Bp = B + (size_t)bk * 512 + n0 + bn;

    float* As0 = smf;            float* Bs0 = smf + 4096;
    float* As1 = smf + 8192;     float* Bs1 = smf + 12288;
    uint32_t bu0 = smem_u32(Bs0 + bk * 128 + bn);
    uint32_t bu1 = smem_u32(Bs1 + bk * 128 + bn);

    unsigned long long acc[8][4];
    #pragma unroll
    for (int i = 0; i < 8; i++)
        #pragma unroll
        for (int p = 0; p < 4; p++) acc[i][p] = 0ULL;

    {
        #pragma unroll
        for (int o = 0; o < 4; o++) {
            float4 a = aval ? *(const float4*)(Ap + o * 8) : make_float4(0.f, 0.f, 0.f, 0.f);
            As0[(ak + o * 8 + 0) * 128 + ar] = a.x;
            As0[(ak + o * 8 + 1) * 128 + ar] = a.y;
            As0[(ak + o * 8 + 2) * 128 + ar] = a.z;
            As0[(ak + o * 8 + 3) * 128 + ar] = a.w;
            cp16(bu0 + o * 8 * 128 * 4, Bp + (size_t)o * 8 * 512);
        }
        CP_COMMIT();
    }

    for (int kt = 0; kt < NT; kt++) {
        const int buf = kt & 1;
        float* Asc = buf ? As1 : As0;
        float* Bsc = buf ? Bs1 : Bs0;
        CP_WAIT0();
        __syncthreads();
        const bool nxt = (kt + 1) < NT;
        float4 avn[4];
        if (nxt) {
            #pragma unroll
            for (int o = 0; o < 4; o++) {
                avn[o] = aval ? *(const float4*)(Ap + (size_t)(kt + 1) * 32 + o * 8)
                              : make_float4(0.f, 0.f, 0.f, 0.f);
                cp16((buf ? bu0 : bu1) + o * 8 * 128 * 4,
                     Bp + ((size_t)(kt + 1) * 32 + o * 8) * 512);
            }
            CP_COMMIT();
        }
        #pragma unroll
        for (int kk = 0; kk < 32; kk++) {
            float ra[8], rb[8];
            *(float4*)&ra[0] = *(const float4*)&Asc[kk * 128 + (tm << 2)];
            *(float4*)&ra[4] = *(const float4*)&Asc[kk * 128 + 64 + (tm << 2)];
            *(float4*)&rb[0] = *(const float4*)&Bsc[kk * 128 + (tn << 2)];
            *(float4*)&rb[4] = *(const float4*)&Bsc[kk * 128 + 64 + (tn << 2)];
            unsigned long long ap[8], bp[4];
            #pragma unroll
            for (int i = 0; i < 8; i++) ap[i] = pk2(ra[i], ra[i]);
            bp[0] = pk2(rb[0], rb[1]); bp[1] = pk2(rb[2], rb[3]);
            bp[2] = pk2(rb[4], rb[5]); bp[3] = pk2(rb[6], rb[7]);
            #pragma unroll
            for (int i = 0; i < 8; i++)
                #pragma unroll
                for (int p = 0; p < 4; p++) ffma2(acc[i][p], ap[i], bp[p]);
        }
        if (nxt) {
            float* Asn = buf ? As0 : As1;
            #pragma unroll
            for (int o = 0; o < 4; o++) {
                Asn[(ak + o * 8 + 0) * 128 + ar] = avn[o].x;
                Asn[(ak + o * 8 + 1) * 128 + ar] = avn[o].y;
                Asn[(ak + o * 8 + 2) * 128 + ar] = avn[o].z;
                Asn[(ak + o * 8 + 3) * 128 + ar] = avn[o].w;
            }
        }
    }

    #pragma unroll
    for (int i = 0; i < 8; i++) {
        const int m = m0 + ((i < 4) ? (tm << 2) + i : 64 + (tm << 2) + i - 4);
        if (m >= Mrows) continue;
        #pragma unroll
        for (int p = 0; p < 4; p++) {
            float2 v = upk2(acc[i][p]);
            const int nl = (p < 2) ? (tn << 2) + 2 * p : 64 + (tn << 2) + 2 * (p - 2);
            const int n = n0 + nl;
            const int d = n >> 1;
            float a = tanhf(v.x + bias0[d]);
            float g = 1.f / (1.f + expf(-(v.y + bias1[d])));
            Out[(size_t)m * 256 + d] = a * g;
        }
    }
}

// ---------------- A = ag @ Wc + bc (sequential d order, FROZEN) ----------------
__global__ void __launch_bounds__(256) attn_scores_k(
    const float* __restrict__ ag, const float* __restrict__ Wc,
    const float* __restrict__ bc, float* __restrict__ At)
{
    __shared__ float sW[DDIM * KHEADS];
    __shared__ float sb[KHEADS];
    for (int i = threadIdx.x; i < DDIM * KHEADS; i += blockDim.x) sW[i] = Wc[i];
    if (threadIdx.x < KHEADS) sb[threadIdx.x] = bc[threadIdx.x];
    __syncthreads();
    int n = blockIdx.x * blockDim.x + threadIdx.x;
    if (n >= NPATCH) return;
    float acc[KHEADS];
    #pragma unroll
    for (int k = 0; k < KHEADS; k++) acc[k] = sb[k];
    const float4* r = (const float4*)(ag + (size_t)n * DDIM);
    #pragma unroll 4
    for (int q = 0; q < DDIM / 4; q++) {
        float4 v = r[q];
        int d = q * 4;
        #pragma unroll
        for (int k = 0; k < KHEADS; k++) {
            acc[k] = fmaf(v.x, sW[(d + 0) * KHEADS + k], acc[k]);
            acc[k] = fmaf(v.y, sW[(d + 1) * KHEADS + k], acc[k]);
            acc[k] = fmaf(v.z, sW[(d + 2) * KHEADS + k], acc[k]);
            acc[k] = fmaf(v.w, sW[(d + 3) * KHEADS + k], acc[k]);
        }
    }
    #pragma unroll
    for (int k = 0; k < KHEADS; k++) At[(size_t)k * NPATCH + n] = acc[k];
}

// ---------------- top-k stage 1 (+ zero g_M) ----------------
__global__ void __launch_bounds__(1024) topk_pivot_k(const float* __restrict__ At,
                                                     float* __restrict__ Mout) {
    const int k = blockIdx.x, tid = threadIdx.x;
    __shared__ unsigned sk[2048];
    if (tid < HDIM) Mout[k * HDIM + tid] = 0.f;
    for (int j = tid; j < 2048; j += 1024)
        sk[j] = (j < 1536) ? f2u(At[(size_t)k * NPATCH + j * 65]) : 0u;
    __syncthreads();
    for (int kk = 2; kk <= 2048; kk <<= 1) {
        for (int j = kk >> 1; j > 0; j >>= 1) {
            int i = ((tid & ~(j - 1)) << 1) | (tid & (j - 1));
            int l = i | j;
            unsigned a = sk[i], b = sk[l];
            bool asc = (i & kk) != 0;
            if (asc ? (a > b) : (a < b)) { sk[i] = b; sk[l] = a; }
            __syncthreads();
        }
    }
    if (tid == 0) {
        g_pivot[k] = sk[63];
        g_ccnt[k] = 0;
    }
}

// ---------------- top-k stage 2: candidate gather ----------------
__global__ void __launch_bounds__(256) topk_gather_k(const float* __restrict__ At) {
    const int k = blockIdx.y;
    const unsigned pivot = g_pivot[k];
    const float* row = At + (size_t)k * NPATCH;
    const int base = blockIdx.x * 2500;
    for (int j = base + threadIdx.x; j < base + 2500; j += 256) {
        unsigned u = f2u(row[j]);
        if (u >= pivot) {
            unsigned p = atomicAdd(&g_ccnt[k], 1u);
            if (p < CANDC)
                g_cand[(size_t)k * CANDC + p] =
                    ((unsigned long long)u << 32) | (unsigned)(~(unsigned)j);
        }
    }
}

// ---- top-k stage 3: sort + mask + post-mask row max ----
__global__ void __launch_bounds__(1024) topk_mask2_k(
    float* __restrict__ At, const int* __restrict__ rand_sel)
{
    extern __shared__ unsigned long long buf[];
    unsigned char* mk = (unsigned char*)(buf + 8192);
    const int k = blockIdx.x, tid = threadIdx.x;
    unsigned cnt = g_ccnt[k]; if (cnt > CANDC) cnt = CANDC;
    for (int i = tid; i < 8192; i += 1024)
        buf[i] = (i < (int)cnt) ? g_cand[(size_t)k * CANDC + i] : 0ULL;
    if (tid < 1024) mk[tid] = 0;
    __syncthreads();
    for (int kk = 2; kk <= 8192; kk <<= 1) {
        for (int j = kk >> 1; j > 0; j >>= 1) {
            for (int w = tid; w < 4096; w += 1024) {
                int i = ((w & ~(j - 1)) << 1) | (w & (j - 1));
                int l = i | j;
                unsigned long long a = buf[i], b = buf[l];
                bool asc = (i & kk) != 0;
                if (asc ? (a > b) : (a < b)) { buf[i] = b; buf[l] = a; }
            }
            __syncthreads();
        }
    }
    float* row = At + (size_t)k * NPATCH;
    for (int j = tid; j < MDROP; j += 1024) {
        int rs = rand_sel[k * MDROP + j];
        mk[rs] = 1;
        int idx = (int)(~(unsigned)(buf[rs] & 0xFFFFFFFFULL));
        row[idx] = NEGV;
    }
    __syncthreads();
    if (tid == 0) {
        int r = 0;
        while (mk[r]) r++;
        g_mxu[k] = (unsigned)(buf[r] >> 32);
    }
}

// ---- sum pass: write A_raw + Asm = exp(v-mx) (unnormalized) + partial sums ----
__global__ void __launch_bounds__(256) sumexp_k(
    const float* __restrict__ At, float* __restrict__ Asm, float* __restrict__ outA)
{
    const int k = blockIdx.y;
    const float mx = u2f(g_mxu[k]);
    const float* row = At + (size_t)k * NPATCH;
    const int base = blockIdx.x * 2500;
    float sm = 0.f;
    for (int j = base + threadIdx.x; j < base + 2500; j += 256) {
        float v = row[j];
        outA[(size_t)k * NPATCH + j] = v;
        float e = expf(v - mx);
        Asm[(size_t)k * NPATCH + j] = e;
        sm += e;
    }
    __shared__ float sred[8];
    #pragma unroll
    for (int o = 16; o; o >>= 1) sm += __shfl_xor_sync(0xffffffffu, sm, o);
    if ((threadIdx.x & 31) == 0) sred[threadIdx.x >> 5] = sm;
    __syncthreads();
    if (threadIdx.x == 0) {
        float s = 0.f;
        for (int w = 0; w < 8; w++) s += sred[w];
        g_psum[k][blockIdx.x] = s;
    }
}

// ---------------- M_raw = Asm_unnorm @ x ----------------
#define PCHUNK 400
__global__ void __launch_bounds__(128) pool_k(
    const float* __restrict__ Asm, const float* __restrict__ x, float* __restrict__ Mout)
{
    const int h = blockIdx.x * 128 + threadIdx.x;
    const int n0 = blockIdx.y * PCHUNK;
    float acc[KHEADS] = {0.f, 0.f, 0.f, 0.f, 0.f};
    for (int n = n0; n < n0 + PCHUNK; n++) {
        float xv = x[(size_t)n * HDIM + h];
        #pragma unroll
        for (int kk = 0; kk < KHEADS; kk++)
            acc[kk] = fmaf(Asm[(size_t)kk * NPATCH + n], xv, acc[kk]);
    }
    #pragma unroll
    for (int kk = 0; kk < KHEADS; kk++) atomicAdd(&Mout[kk * HDIM + h], acc[kk]);
}

// ---------------- final heads (deferred 1/s_k) ----------------
__global__ void __launch_bounds__(512) final_k(
    const float* __restrict__ Mbuf,
    const float* __restrict__ Wcls, const float* __restrict__ bcls,
    const float* __restrict__ Wbag, const float* __restrict__ bbag,
    float* __restrict__ out)
{
    const int tid = threadIdx.x;
    float inv[KHEADS];
    #pragma unroll
    for (int k = 0; k < KHEADS; k++) {
        float s = 0.f;
        for (int w = 0; w < 40; w++) s += g_psum[k][w];
        inv[k] = 1.f / s;
    }
    float m[KHEADS];
    #pragma unroll
    for (int k = 0; k < KHEADS; k++) m[k] = Mbuf[k * HDIM + tid] * inv[k];
    float bagf = 0.2f * (m[0] + m[1] + m[2] + m[3] + m[4]);
    float v[12];
    #pragma unroll
    for (int k = 0; k < KHEADS; k++)
        #pragma unroll
        for (int c = 0; c < NCLS; c++)
            v[k * 2 + c] = m[k] * Wcls[(size_t)k * HDIM * NCLS + tid * NCLS + c];
    v[10] = bagf * Wbag[tid * NCLS + 0];
    v[11] = bagf * Wbag[tid * NCLS + 1];

    __shared__ float red[16][12];
    #pragma unroll
    for (int e = 0; e < 12; e++)
        #pragma unroll
        for (int o = 16; o; o >>= 1) v[e] += __shfl_xor_sync(0xffffffffu, v[e], o);
    if ((tid & 31) == 0)
        for (int e = 0; e < 12; e++) red[tid >> 5][e] = v[e];
    __syncthreads();
    if (tid == 0) {
        float s[12];
        for (int e = 0; e < 12; e++) { s[e] = 0.f; for (int w = 0; w < 16; w++) s[e] += red[w][e]; }
        for (int k = 0; k < KHEADS; k++)
            for (int c = 0; c < NCLS; c++)
                out[k * 2 + c] = s[k * 2 + c] + bcls[k * 2 + c];
        out[10] = s[10] + bbag[0];
        out[11] = s[11] + bbag[1];
    }
}

// ---------------- launch ----------------
extern "C" void kernel_launch(void* const* d_in, const int* in_sizes, int n_in,
                              void* d_out, int out_size)
{
    const float* h    = (const float*)d_in[0];
    const int*   rsel = (const int*)  d_in[1];
    const float* W1   = (const float*)d_in[2];
    const float* b1   = (const float*)d_in[3];
    const float* Wa   = (const float*)d_in[4];
    const float* ba   = (const float*)d_in[5];
    const float* Wb   = (const float*)d_in[6];
    const float* bb   = (const float*)d_in[7];
    const float* Wc   = (const float*)d_in[8];
    const float* bc   = (const float*)d_in[9];
    const float* Wcls = (const float*)d_in[10];
    const float* bcls = (const float*)d_in[11];
    const float* Wbag = (const float*)d_in[12];
    const float* bbag = (const float*)d_in[13];
    float* out = (float*)d_out;

    float *px, *pag, *pAt, *pAsm, *pM, *pWab;
    cudaGetSymbolAddress((void**)&px,   g_x);
    cudaGetSymbolAddress((void**)&pag,  g_ag);
    cudaGetSymbolAddress((void**)&pAt,  g_At);
    cudaGetSymbolAddress((void**)&pAsm, g_Asm);
    cudaGetSymbolAddress((void**)&pM,   g_M);
    cudaGetSymbolAddress((void**)&pWab, g_Wab);

    cudaFuncSetAttribute((const void*)f2gemm1w,
                         cudaFuncAttributeMaxDynamicSharedMemorySize, G1SM_BYTES);
    cudaFuncSetAttribute((const void*)f2gemm2,
                         cudaFuncAttributeMaxDynamicSharedMemorySize, GSM_BYTES);
    cudaFuncSetAttribute((const void*)topk_mask2_k,
                         cudaFuncAttributeMaxDynamicSharedMemorySize, 8192 * 8 + 1024);

    prep_wab<<<512, 256>>>(Wa, Wb);

    const int MBLK = (NPATCH + 127) / 128;   // 782
    f2gemm1w<<<dim3(2, MBLK), 256, G1SM_BYTES>>>(h, W1, b1, px, NPATCH);
    f2gemm2<<<dim3(4, MBLK), 256, GSM_BYTES>>>(px, pWab, ba, bb, pag, NPATCH);

    attn_scores_k<<<(NPATCH + 255) / 256, 256>>>(pag, Wc, bc, pAt);

    topk_pivot_k<<<KHEADS, 1024>>>(pAt, pM);
    topk_gather_k<<<dim3(40, KHEADS), 256>>>(pAt);
    topk_mask2_k<<<KHEADS, 1024, 8192 * 8 + 1024>>>(pAt, rsel);

    sumexp_k<<<dim3(40, KHEADS), 256>>>(pAt, pAsm, out + 12);

    pool_k<<<dim3(HDIM / 128, NPATCH / PCHUNK), 128>>>(pAsm, px, pM);
    final_k<<<1, HDIM>>>(pM, Wcls, bcls, Wbag, bbag, out);
}